// round 1
// baseline (speedup 1.0000x reference)
#include <cuda_runtime.h>
#include <math.h>
#include <stdint.h>

#define N 4096
#define D 512
#define TAU_INV 5.0f
// quantile index = 0.8*(N-1) = 3276 exactly; count of elements >= thr = N-3276
#define KSEL 820
#define NB 32  // 4096/128 tiles per dim

// ---- device scratch (allocation-free) ----
__device__ float g_hn[(size_t)N * D];        // normalized hard-neg embeddings (8 MB)
__device__ float g_S[(size_t)N * N];         // hard_neg cosine sim matrix (64 MB)
__device__ int   g_partner[N];
__device__ int   g_pneg[N];
__device__ float g_posexp[N];                // per-pair exp(hard_pos_cos/TAU)
__device__ float g_negsum[N];                // per-row hard_neg_sum

// ---------------------------------------------------------------- init
__global__ void k_init(float* out) {
    int i = blockIdx.x * blockDim.x + threadIdx.x;
    if (i < N) g_partner[i] = -1;
    if (i == 0) out[0] = 0.0f;
}

__global__ void k_scatter(const int* __restrict__ pairs, int P) {
    int k = blockIdx.x * blockDim.x + threadIdx.x;
    if (k < P) g_partner[pairs[2 * k]] = pairs[2 * k + 1];
}

// partner_neg[i] = max j with (j != i) && (partner[j] != i); -1 wraps to N-1
__global__ void k_pneg() {
    int i = blockIdx.x * blockDim.x + threadIdx.x;
    if (i >= N) return;
    int j = N - 1;
    while (j >= 0 && (j == i || g_partner[j] == i)) j--;
    g_pneg[i] = (j < 0) ? (N - 1) : j;
}

// ---------------------------------------------------------------- hard-neg normalize
__global__ __launch_bounds__(128) void k_hn(const float* __restrict__ E) {
    int i = blockIdx.x;
    int pn = g_pneg[i];
    const float* ei = E + (size_t)i * D;
    const float* ep = E + (size_t)pn * D;
    float v[4];
    float ss = 0.0f;
#pragma unroll
    for (int q = 0; q < 4; q++) {
        int d = threadIdx.x + q * 128;
        float m = 0.5f * ei[d] + 0.5f * ep[d];  // LAM_NEG = 0.5
        v[q] = m;
        ss += m * m;
    }
    __shared__ float red[4];
    for (int off = 16; off; off >>= 1) ss += __shfl_down_sync(0xffffffffu, ss, off);
    if ((threadIdx.x & 31) == 0) red[threadIdx.x >> 5] = ss;
    __syncthreads();
    if (threadIdx.x == 0) {
        float t = red[0] + red[1] + red[2] + red[3];
        red[0] = 1.0f / fmaxf(sqrtf(t), 1e-8f);
    }
    __syncthreads();
    float inv = red[0];
#pragma unroll
    for (int q = 0; q < 4; q++) {
        int d = threadIdx.x + q * 128;
        g_hn[(size_t)i * D + d] = v[q] * inv;
    }
}

// ---------------------------------------------------------------- pos term per pair
__global__ __launch_bounds__(128) void k_pos(const float* __restrict__ E,
                                             const int* __restrict__ pairs) {
    int k = blockIdx.x;
    int i = pairs[2 * k], j = pairs[2 * k + 1];
    int pi = g_partner[i], pj = g_partner[j];
    const float* Ei  = E + (size_t)i * D;
    const float* Ej  = E + (size_t)j * D;
    const float* Epi = E + (size_t)((pi >= 0) ? pi : 0) * D;
    const float* Epj = E + (size_t)((pj >= 0) ? pj : 0) * D;
    float daa = 0.f, dab = 0.f, dbb = 0.f;
#pragma unroll
    for (int q = 0; q < 4; q++) {
        int d = threadIdx.x + q * 128;
        float a = (pi >= 0) ? (1.5f * Ei[d] - 0.5f * Epi[d]) : Ei[d];  // LAM_POS = 1.5
        float b = (pj >= 0) ? (1.5f * Ej[d] - 0.5f * Epj[d]) : Ej[d];
        daa = fmaf(a, a, daa);
        dab = fmaf(a, b, dab);
        dbb = fmaf(b, b, dbb);
    }
    __shared__ float raa[4], rab[4], rbb[4];
    unsigned fm = 0xffffffffu;
    for (int off = 16; off; off >>= 1) {
        daa += __shfl_down_sync(fm, daa, off);
        dab += __shfl_down_sync(fm, dab, off);
        dbb += __shfl_down_sync(fm, dbb, off);
    }
    int w = threadIdx.x >> 5, l = threadIdx.x & 31;
    if (l == 0) { raa[w] = daa; rab[w] = dab; rbb[w] = dbb; }
    __syncthreads();
    if (threadIdx.x == 0) {
        float A = raa[0] + raa[1] + raa[2] + raa[3];
        float B = rab[0] + rab[1] + rab[2] + rab[3];
        float C = rbb[0] + rbb[1] + rbb[2] + rbb[3];
        float cosv = B / (fmaxf(sqrtf(A), 1e-8f) * fmaxf(sqrtf(C), 1e-8f));
        g_posexp[k] = expf(cosv * TAU_INV);
    }
}

// ---------------------------------------------------------------- symmetric SGEMM: S = HN * HN^T
// Upper-triangle tile grid (528 CTAs), mirror-store off-diagonal tiles.
__global__ __launch_bounds__(256, 2) void k_gemm() {
    const float* __restrict__ HN = g_hn;
    float* __restrict__ S = g_S;

    int t = blockIdx.x;
    int by = 0, rem = t;
    while (rem >= (NB - by)) { rem -= (NB - by); ++by; }
    int bx = by + rem;  // bx >= by

    __shared__ __align__(16) float As[16][132];
    __shared__ __align__(16) float Bs[16][132];

    int tid = threadIdx.x;
    int tx = tid & 15, ty = tid >> 4;
    int lr = tid >> 2, lc = (tid & 3) << 2;

    const float* Arow = HN + (size_t)by * 128 * D;
    const float* Brow = HN + (size_t)bx * 128 * D;

    float acc[8][8];
#pragma unroll
    for (int m = 0; m < 8; m++)
#pragma unroll
        for (int n = 0; n < 8; n++) acc[m][n] = 0.0f;

    for (int k0 = 0; k0 < D; k0 += 16) {
        float4 a0 = *(const float4*)(Arow + (size_t)lr * D + k0 + lc);
        float4 a1 = *(const float4*)(Arow + (size_t)(lr + 64) * D + k0 + lc);
        float4 b0 = *(const float4*)(Brow + (size_t)lr * D + k0 + lc);
        float4 b1 = *(const float4*)(Brow + (size_t)(lr + 64) * D + k0 + lc);
        __syncthreads();
        As[lc + 0][lr] = a0.x; As[lc + 1][lr] = a0.y; As[lc + 2][lr] = a0.z; As[lc + 3][lr] = a0.w;
        As[lc + 0][lr + 64] = a1.x; As[lc + 1][lr + 64] = a1.y; As[lc + 2][lr + 64] = a1.z; As[lc + 3][lr + 64] = a1.w;
        Bs[lc + 0][lr] = b0.x; Bs[lc + 1][lr] = b0.y; Bs[lc + 2][lr] = b0.z; Bs[lc + 3][lr] = b0.w;
        Bs[lc + 0][lr + 64] = b1.x; Bs[lc + 1][lr + 64] = b1.y; Bs[lc + 2][lr + 64] = b1.z; Bs[lc + 3][lr + 64] = b1.w;
        __syncthreads();
#pragma unroll
        for (int kk = 0; kk < 16; kk++) {
            float4 av0 = *(const float4*)&As[kk][ty * 8];
            float4 av1 = *(const float4*)&As[kk][ty * 8 + 4];
            float4 bv0 = *(const float4*)&Bs[kk][tx * 8];
            float4 bv1 = *(const float4*)&Bs[kk][tx * 8 + 4];
            float a[8] = {av0.x, av0.y, av0.z, av0.w, av1.x, av1.y, av1.z, av1.w};
            float b[8] = {bv0.x, bv0.y, bv0.z, bv0.w, bv1.x, bv1.y, bv1.z, bv1.w};
#pragma unroll
            for (int m = 0; m < 8; m++)
#pragma unroll
                for (int n = 0; n < 8; n++) acc[m][n] = fmaf(a[m], b[n], acc[m][n]);
        }
    }

    int r0 = by * 128 + ty * 8, c0 = bx * 128 + tx * 8;
#pragma unroll
    for (int m = 0; m < 8; m++) {
        float4 s0 = make_float4(acc[m][0], acc[m][1], acc[m][2], acc[m][3]);
        float4 s1 = make_float4(acc[m][4], acc[m][5], acc[m][6], acc[m][7]);
        float* p = S + (size_t)(r0 + m) * N + c0;
        *(float4*)p = s0;
        *(float4*)(p + 4) = s1;
    }
    if (bx != by) {  // mirror transpose-store
#pragma unroll
        for (int n = 0; n < 8; n++) {
            float4 s0 = make_float4(acc[0][n], acc[1][n], acc[2][n], acc[3][n]);
            float4 s1 = make_float4(acc[4][n], acc[5][n], acc[6][n], acc[7][n]);
            float* p = S + (size_t)(c0 + n) * N + r0;
            *(float4*)p = s0;
            *(float4*)(p + 4) = s1;
        }
    }
}

// ---------------------------------------------------------------- per-row top-K selection + sum
__device__ __forceinline__ int bin_of(float v) {
    int b = (int)((v + 1.0f) * 128.0f);
    return b < 0 ? 0 : (b > 255 ? 255 : b);
}

__global__ __launch_bounds__(512) void k_select() {
    __shared__ float sval[N];         // 16 KB
    __shared__ int   hist[256];
    __shared__ float list[1024];
    __shared__ int   s_cnt, s_b, s_kp;
    __shared__ float s_thr;
    __shared__ float warpsum[16];

    int row = blockIdx.x;
    int tid = threadIdx.x;
    int pi = g_partner[row];
    const float* Sr = g_S + (size_t)row * N;

    if (tid < 256) hist[tid] = 0;
    if (tid == 0) { s_cnt = 0; s_thr = -3.0f; s_b = 0; s_kp = 1; }
    __syncthreads();

    // pass 1: mask, stash in smem, histogram on value in [-1,1]
#pragma unroll
    for (int q = 0; q < 8; q++) {
        int j = tid + q * 512;
        float v = Sr[j];
        if (j == row || j == pi) v = -2.0f;  // masked (diag | pos) -> below any real sim
        sval[j] = v;
        atomicAdd(&hist[bin_of(v)], 1);
    }
    __syncthreads();

    // find bin containing the KSEL-th largest value
    if (tid < 32) {
        int lane = tid;
        int c = 0;
#pragma unroll
        for (int q = 0; q < 8; q++) c += hist[lane * 8 + q];
        int suf = c;  // inclusive suffix sum over lane chunks (from high lanes)
#pragma unroll
        for (int off = 1; off < 32; off <<= 1) {
            int o = __shfl_down_sync(0xffffffffu, suf, off);
            if (lane + off < 32) suf += o;
        }
        int above = suf - c;
        if (above < KSEL && KSEL <= suf) {
            int rem = KSEL - above;
            int b = lane * 8;
            for (int q = 7; q >= 0; q--) {
                int h = hist[lane * 8 + q];
                if (rem <= h) { b = lane * 8 + q; break; }
                rem -= h;
            }
            s_b = b;
            s_kp = rem;  // rank (from top) inside boundary bin, 1-based
        }
    }
    __syncthreads();
    int bsel = s_b, kp = s_kp;

    // gather boundary-bin candidates
#pragma unroll
    for (int q = 0; q < 8; q++) {
        int j = tid + q * 512;
        float v = sval[j];
        if (bin_of(v) == bsel) {
            int idx = atomicAdd(&s_cnt, 1);
            if (idx < 1024) list[idx] = v;
        }
    }
    __syncthreads();
    int cn = min(s_cnt, 1024);

    // exact kp-th largest within boundary bin (tie-aware)
    for (int t2 = tid; t2 < cn; t2 += 512) {
        float v = list[t2];
        int gt = 0, eq = 0;
        for (int m = 0; m < cn; m++) {
            float w = list[m];
            gt += (w > v);
            eq += (w == v);
        }
        if (gt < kp && kp <= gt + eq) s_thr = v;
    }
    __syncthreads();
    float thr = s_thr;

    // sum exp(s/TAU) over s >= thr  (== top-KSEL incl. ties, matching reference)
    float acc = 0.0f;
#pragma unroll
    for (int q = 0; q < 8; q++) {
        float v = sval[tid + q * 512];
        if (v >= thr) acc += __expf(v * TAU_INV);
    }
    for (int off = 16; off; off >>= 1) acc += __shfl_down_sync(0xffffffffu, acc, off);
    if ((tid & 31) == 0) warpsum[tid >> 5] = acc;
    __syncthreads();
    if (tid < 16) {
        float x = warpsum[tid];
        for (int off = 8; off; off >>= 1) x += __shfl_down_sync(0x0000ffffu, x, off);
        if (tid == 0) g_negsum[row] = x;
    }
}

// ---------------------------------------------------------------- final loss reduction
__global__ void k_loss(const int* __restrict__ pairs, float* out, int P) {
    int k = blockIdx.x * blockDim.x + threadIdx.x;
    if (k >= P) return;
    int i = pairs[2 * k];
    float pz = g_posexp[k];
    float ns = g_negsum[i];
    float loss = -logf(pz / (pz + ns));
    atomicAdd(out, loss * (1.0f / (float)P));
}

// ---------------------------------------------------------------- launch
extern "C" void kernel_launch(void* const* d_in, const int* in_sizes, int n_in,
                              void* d_out, int out_size) {
    const float* E = (const float*)d_in[0];
    const int* pairs = (const int*)d_in[1];
    float* out = (float*)d_out;
    int P = in_sizes[1] / 2;

    k_init<<<(N + 255) / 256, 256>>>(out);
    k_scatter<<<(P + 255) / 256, 256>>>(pairs, P);
    k_pneg<<<(N + 255) / 256, 256>>>();
    k_hn<<<N, 128>>>(E);
    k_pos<<<P, 128>>>(E, pairs);
    k_gemm<<<NB * (NB + 1) / 2, 256>>>();
    k_select<<<N, 512>>>();
    k_loss<<<(P + 255) / 256, 256>>>(pairs, out, P);
}

// round 3
// speedup vs baseline: 1.5162x; 1.5162x over previous
#include <cuda_runtime.h>
#include <math.h>
#include <stdint.h>

#define N 4096
#define D 512
#define TAU_INV 5.0f
#define KSEL 820          // N - floor(0.8*(N-1)) = 4096 - 3276
#define NB 32             // 128-wide tiles per dim
#define KSLAB 32
#define STAGES 16         // D / KSLAB
#define NBINS 512
#define KSBLK 1032        // floats per K-step sub-block (1024 + 8 pad, breaks STS conflicts)
#define ABYTES 4128       // 4 * KSBLK floats per matrix slab
#define BUFF 8256         // floats per stage buffer (A + B)
#define SMEM_GEMM_BYTES 69632

// ---- device scratch (allocation-free) ----
__device__ float g_hn[(size_t)N * D];    // tf32-rounded normalized hard-neg embeddings
__device__ float g_S[(size_t)N * N];
__device__ int   g_partner[N];
__device__ int   g_pneg[N];
__device__ float g_posexp[N];
__device__ float g_negsum[N];

// ---------------------------------------------------------------- init
__global__ void k_init(float* out) {
    int i = blockIdx.x * blockDim.x + threadIdx.x;
    if (i < N) g_partner[i] = -1;
    if (i == 0) out[0] = 0.0f;
}

__global__ void k_scatter(const int* __restrict__ pairs, int P) {
    int k = blockIdx.x * blockDim.x + threadIdx.x;
    if (k < P) g_partner[pairs[2 * k]] = pairs[2 * k + 1];
}

__global__ void k_pneg() {
    int i = blockIdx.x * blockDim.x + threadIdx.x;
    if (i >= N) return;
    int j = N - 1;
    while (j >= 0 && (j == i || g_partner[j] == i)) j--;
    g_pneg[i] = (j < 0) ? (N - 1) : j;
}

// ---------------------------------------------------------------- hard-neg normalize (+ tf32 round)
__global__ __launch_bounds__(128) void k_hn(const float* __restrict__ E) {
    int i = blockIdx.x;
    int pn = g_pneg[i];
    const float* ei = E + (size_t)i * D;
    const float* ep = E + (size_t)pn * D;
    float v[4];
    float ss = 0.0f;
#pragma unroll
    for (int q = 0; q < 4; q++) {
        int d = threadIdx.x + q * 128;
        float m = 0.5f * ei[d] + 0.5f * ep[d];
        v[q] = m;
        ss += m * m;
    }
    __shared__ float red[4];
    for (int off = 16; off; off >>= 1) ss += __shfl_down_sync(0xffffffffu, ss, off);
    if ((threadIdx.x & 31) == 0) red[threadIdx.x >> 5] = ss;
    __syncthreads();
    if (threadIdx.x == 0) {
        float t = red[0] + red[1] + red[2] + red[3];
        red[0] = 1.0f / fmaxf(sqrtf(t), 1e-8f);
    }
    __syncthreads();
    float inv = red[0];
#pragma unroll
    for (int q = 0; q < 4; q++) {
        int d = threadIdx.x + q * 128;
        float x = v[q] * inv;
        uint32_t u;
        asm("cvt.rna.tf32.f32 %0, %1;" : "=r"(u) : "f"(x));
        g_hn[(size_t)i * D + d] = __uint_as_float(u);
    }
}

// ---------------------------------------------------------------- pos term per pair (fp32 exact)
__global__ __launch_bounds__(128) void k_pos(const float* __restrict__ E,
                                             const int* __restrict__ pairs) {
    int k = blockIdx.x;
    int i = pairs[2 * k], j = pairs[2 * k + 1];
    int pi = g_partner[i], pj = g_partner[j];
    const float* Ei  = E + (size_t)i * D;
    const float* Ej  = E + (size_t)j * D;
    const float* Epi = E + (size_t)((pi >= 0) ? pi : 0) * D;
    const float* Epj = E + (size_t)((pj >= 0) ? pj : 0) * D;
    float daa = 0.f, dab = 0.f, dbb = 0.f;
#pragma unroll
    for (int q = 0; q < 4; q++) {
        int d = threadIdx.x + q * 128;
        float a = (pi >= 0) ? (1.5f * Ei[d] - 0.5f * Epi[d]) : Ei[d];
        float b = (pj >= 0) ? (1.5f * Ej[d] - 0.5f * Epj[d]) : Ej[d];
        daa = fmaf(a, a, daa);
        dab = fmaf(a, b, dab);
        dbb = fmaf(b, b, dbb);
    }
    __shared__ float raa[4], rab[4], rbb[4];
    unsigned fm = 0xffffffffu;
    for (int off = 16; off; off >>= 1) {
        daa += __shfl_down_sync(fm, daa, off);
        dab += __shfl_down_sync(fm, dab, off);
        dbb += __shfl_down_sync(fm, dbb, off);
    }
    int w = threadIdx.x >> 5, l = threadIdx.x & 31;
    if (l == 0) { raa[w] = daa; rab[w] = dab; rbb[w] = dbb; }
    __syncthreads();
    if (threadIdx.x == 0) {
        float A = raa[0] + raa[1] + raa[2] + raa[3];
        float B = rab[0] + rab[1] + rab[2] + rab[3];
        float C = rbb[0] + rbb[1] + rbb[2] + rbb[3];
        float cosv = B / (fmaxf(sqrtf(A), 1e-8f) * fmaxf(sqrtf(C), 1e-8f));
        g_posexp[k] = expf(cosv * TAU_INV);
    }
}

// ---------------------------------------------------------------- tf32 mma.sync GEMM
__device__ __forceinline__ void mma8(float* c, const uint32_t* a, const uint32_t* b) {
    asm volatile(
        "mma.sync.aligned.m16n8k8.row.col.f32.tf32.tf32.f32 "
        "{%0,%1,%2,%3}, {%4,%5,%6,%7}, {%8,%9}, {%0,%1,%2,%3};"
        : "+f"(c[0]), "+f"(c[1]), "+f"(c[2]), "+f"(c[3])
        : "r"(a[0]), "r"(a[1]), "r"(a[2]), "r"(a[3]), "r"(b[0]), "r"(b[1]));
}

// S = HN * HN^T, upper-triangle 128x128 tiles + mirror store.
// SMEM: two stage buffers (fragment-major layout), then reused as 128x132 epilogue tile.
__global__ __launch_bounds__(256) void k_gemm_mma() {
    extern __shared__ float sm[];
    int tid = threadIdx.x;
    int lane = tid & 31, warp = tid >> 5;
    int wm = warp >> 2, wn = warp & 3;   // warp grid 2(M) x 4(N), warp tile 64x32

    int t = blockIdx.x, by = 0, rem = t;
    while (rem >= (NB - by)) { rem -= (NB - by); ++by; }
    int bx = by + rem;   // bx >= by

    const float* Abase = g_hn + (size_t)by * 128 * D;
    const float* Bbase = g_hn + (size_t)bx * 128 * D;

    float acc[4][4][4];
#pragma unroll
    for (int im = 0; im < 4; im++)
#pragma unroll
        for (int in = 0; in < 4; in++)
#pragma unroll
            for (int r = 0; r < 4; r++) acc[im][in][r] = 0.0f;

    float4 ra[4], rb[4];

    auto ldg = [&](int s) {
        int k0 = s * KSLAB;
#pragma unroll
        for (int q = 0; q < 4; q++) {
            int v = tid + q * 256;             // 0..1023
            int row = v >> 3, k4 = (v & 7) << 2;
            ra[q] = *(const float4*)(Abase + (size_t)row * D + k0 + k4);
            rb[q] = *(const float4*)(Bbase + (size_t)row * D + k0 + k4);
        }
    };

    // fragment-major store:
    //  A[ks][mt][lane=((r&7)<<2)|(kk&3)][j=((kk>>2)<<1)|(r>>3)]
    //  B[ks][nt][lane=((n&7)<<2)|(kk&3)][j=(kk>>2)]
    auto sts = [&](int p) {
        float* As = sm + p * BUFF;
        float* Bs = As + ABYTES;
#pragma unroll
        for (int q = 0; q < 4; q++) {
            int v = tid + q * 256;
            int row = v >> 3, k4 = (v & 7) << 2;
            const float* va = (const float*)&ra[q];
            const float* vb = (const float*)&rb[q];
            int ks = k4 >> 3;
            int khi = (k4 & 4) ? 1 : 0;
            int mt = row >> 4, r = row & 15;
            float* pa = As + ks * KSBLK + (((mt << 5) | ((r & 7) << 2)) << 2)
                        + ((khi << 1) | (r >> 3));
            int nt = row >> 3, nn = row & 7;
            float* pb = Bs + ks * KSBLK + (((nt << 5) | (nn << 2)) << 1) + khi;
#pragma unroll
            for (int s2 = 0; s2 < 4; s2++) {
                pa[s2 * 4] = va[s2];
                pb[s2 * 2] = vb[s2];
            }
        }
    };

    auto compute = [&](int p) {
        const float* As = sm + p * BUFF;
        const float* Bs = As + ABYTES;
#pragma unroll
        for (int ks = 0; ks < 4; ks++) {
            uint32_t a[4][4], b[4][2];
#pragma unroll
            for (int im = 0; im < 4; im++) {
                float4 t4 = *(const float4*)(As + ks * KSBLK
                                             + ((((wm * 4 + im) << 5) | lane) << 2));
                a[im][0] = __float_as_uint(t4.x); a[im][1] = __float_as_uint(t4.y);
                a[im][2] = __float_as_uint(t4.z); a[im][3] = __float_as_uint(t4.w);
            }
#pragma unroll
            for (int in = 0; in < 4; in++) {
                float2 t2 = *(const float2*)(Bs + ks * KSBLK
                                             + ((((wn * 4 + in) << 5) | lane) << 1));
                b[in][0] = __float_as_uint(t2.x); b[in][1] = __float_as_uint(t2.y);
            }
#pragma unroll
            for (int im = 0; im < 4; im++)
#pragma unroll
                for (int in = 0; in < 4; in++) mma8(acc[im][in], a[im], b[in]);
        }
    };

    ldg(0);
    for (int s = 0; s < STAGES; s++) {
        int p = s & 1;
        sts(p);
        __syncthreads();
        if (s + 1 < STAGES) ldg(s + 1);
        compute(p);
        __syncthreads();
    }

    // ---- epilogue via 128x132 smem tile (direct + mirror, coalesced) ----
    float* stg = sm;
#pragma unroll
    for (int im = 0; im < 4; im++) {
        int row = wm * 64 + im * 16 + (lane >> 2);
#pragma unroll
        for (int in = 0; in < 4; in++) {
            int col = wn * 32 + in * 8 + (lane & 3) * 2;
            stg[row * 132 + col]           = acc[im][in][0];
            stg[row * 132 + col + 1]       = acc[im][in][1];
            stg[(row + 8) * 132 + col]     = acc[im][in][2];
            stg[(row + 8) * 132 + col + 1] = acc[im][in][3];
        }
    }
    __syncthreads();

    float* __restrict__ S = g_S;
    int r0 = by * 128, c0 = bx * 128;
#pragma unroll
    for (int q = 0; q < 16; q++) {
        int v = tid + q * 256;
        int row = v >> 5, c4 = (v & 31) << 2;
        float4 x = *(const float4*)(stg + row * 132 + c4);
        *(float4*)(S + (size_t)(r0 + row) * N + c0 + c4) = x;
    }
    if (bx != by) {
#pragma unroll
        for (int q = 0; q < 16; q++) {
            int v = tid + q * 256;
            int col = v >> 5, r4 = (v & 31) << 2;
            float4 x;
            x.x = stg[(r4 + 0) * 132 + col];
            x.y = stg[(r4 + 1) * 132 + col];
            x.z = stg[(r4 + 2) * 132 + col];
            x.w = stg[(r4 + 3) * 132 + col];
            *(float4*)(S + (size_t)(c0 + col) * N + r0 + r4) = x;
        }
    }
}

// ---------------------------------------------------------------- per-row top-K selection + sum
__device__ __forceinline__ int bin_of(float v) {
    int b = (int)((v + 1.0f) * 256.0f);
    return b < 0 ? 0 : (b > (NBINS - 1) ? (NBINS - 1) : b);
}

__global__ __launch_bounds__(512) void k_select() {
    __shared__ float sval[N];                        // 16 KB
    __shared__ unsigned short whist[16 * NBINS];     // 16 KB per-warp hist
    __shared__ int   hist[NBINS];                    // 2 KB
    __shared__ float list[2048];                     // 8 KB
    __shared__ int   shist[256];                     // 1 KB sub-histogram
    __shared__ int   s_cnt, s_b, s_kp, s_b2, s_kp2;
    __shared__ float s_thr;
    __shared__ float warpsum[16];

    int row = blockIdx.x;
    int tid = threadIdx.x;
    int lane = tid & 31, w = tid >> 5;
    int pi = g_partner[row];
    const float* Sr = g_S + (size_t)row * N;

    for (int b = tid; b < 16 * NBINS / 2; b += 512) ((unsigned*)whist)[b] = 0u;
    if (tid < 256) shist[tid] = 0;
    if (tid == 0) { s_cnt = 0; s_thr = -3.0f; s_b = 0; s_kp = 1; s_b2 = 0; s_kp2 = 1; }
    __syncthreads();

    // pass 1: mask, stash, per-warp aggregated histogram (no atomics)
    unsigned short* wh = whist + w * NBINS;
#pragma unroll
    for (int q = 0; q < 8; q++) {
        int j = tid + q * 512;
        float v = Sr[j];
        if (j == row || j == pi) v = -2.0f;
        sval[j] = v;
        int b = bin_of(v);
        unsigned mm = __match_any_sync(0xffffffffu, b);
        if ((__ffs(mm) - 1) == lane) wh[b] = (unsigned short)(wh[b] + __popc(mm));
    }
    __syncthreads();

    if (tid < NBINS) {
        int c = 0;
#pragma unroll
        for (int ww = 0; ww < 16; ww++) c += whist[ww * NBINS + tid];
        hist[tid] = c;
    }
    __syncthreads();

    // locate bin containing KSEL-th largest (suffix scan, 16 bins/lane)
    if (tid < 32) {
        int c = 0;
#pragma unroll
        for (int q = 0; q < 16; q++) c += hist[tid * 16 + q];
        int suf = c;
#pragma unroll
        for (int off = 1; off < 32; off <<= 1) {
            int o = __shfl_down_sync(0xffffffffu, suf, off);
            if (tid + off < 32) suf += o;
        }
        int above = suf - c;
        if (above < KSEL && KSEL <= suf) {
            int remk = KSEL - above;
            int b = tid * 16;
            for (int q = 15; q >= 0; q--) {
                int h = hist[tid * 16 + q];
                if (remk <= h) { b = tid * 16 + q; break; }
                remk -= h;
            }
            s_b = b;
            s_kp = remk;
        }
    }
    __syncthreads();
    int bsel = s_b, kp = s_kp;
    float lo = (float)bsel * (1.0f / 256.0f) - 1.0f;

    // gather boundary-bin candidates + sub-histogram (256 sub-bins)
#pragma unroll
    for (int q = 0; q < 8; q++) {
        float v = sval[tid + q * 512];
        if (bin_of(v) == bsel) {
            int idx = atomicAdd(&s_cnt, 1);
            if (idx < 2048) list[idx] = v;
            int sb = (int)((v - lo) * 65536.0f);
            sb = sb < 0 ? 0 : (sb > 255 ? 255 : sb);
            atomicAdd(&shist[sb], 1);
        }
    }
    __syncthreads();
    int cn = min(s_cnt, 2048);

    // locate sub-bin (8 sub-bins/lane)
    if (tid < 32) {
        int c = 0;
#pragma unroll
        for (int q = 0; q < 8; q++) c += shist[tid * 8 + q];
        int suf = c;
#pragma unroll
        for (int off = 1; off < 32; off <<= 1) {
            int o = __shfl_down_sync(0xffffffffu, suf, off);
            if (tid + off < 32) suf += o;
        }
        int above = suf - c;
        if (above < kp && kp <= suf) {
            int remk = kp - above;
            int b = tid * 8;
            for (int q = 7; q >= 0; q--) {
                int h = shist[tid * 8 + q];
                if (remk <= h) { b = tid * 8 + q; break; }
                remk -= h;
            }
            s_b2 = b;
            s_kp2 = remk;
        }
    }
    __syncthreads();
    int sb2 = s_b2, kp2 = s_kp2;

    // exact tie-aware rank within the chosen sub-bin
    for (int t2 = tid; t2 < cn; t2 += 512) {
        float v = list[t2];
        int vs = (int)((v - lo) * 65536.0f);
        vs = vs < 0 ? 0 : (vs > 255 ? 255 : vs);
        if (vs != sb2) continue;
        int gt = 0, eq = 0;
        for (int m = 0; m < cn; m++) {
            float wv = list[m];
            int ws = (int)((wv - lo) * 65536.0f);
            ws = ws < 0 ? 0 : (ws > 255 ? 255 : ws);
            if (ws == sb2) { gt += (wv > v); eq += (wv == v); }
        }
        if (gt < kp2 && kp2 <= gt + eq) s_thr = v;
    }
    __syncthreads();
    float thr = s_thr;

    // sum exp(s/TAU) over s >= thr (== top-KSEL incl. ties)
    float acc = 0.0f;
#pragma unroll
    for (int q = 0; q < 8; q++) {
        float v = sval[tid + q * 512];
        if (v >= thr) acc += __expf(v * TAU_INV);
    }
    for (int off = 16; off; off >>= 1) acc += __shfl_down_sync(0xffffffffu, acc, off);
    if (lane == 0) warpsum[w] = acc;
    __syncthreads();
    if (tid < 16) {
        float x = warpsum[tid];
        for (int off = 8; off; off >>= 1) x += __shfl_down_sync(0x0000ffffu, x, off);
        if (tid == 0) g_negsum[row] = x;
    }
}

// ---------------------------------------------------------------- final loss reduction
__global__ void k_loss(const int* __restrict__ pairs, float* out, int P) {
    int k = blockIdx.x * blockDim.x + threadIdx.x;
    if (k >= P) return;
    int i = pairs[2 * k];
    float pz = g_posexp[k];
    float ns = g_negsum[i];
    float loss = -logf(pz / (pz + ns));
    atomicAdd(out, loss * (1.0f / (float)P));
}

// ---------------------------------------------------------------- launch
extern "C" void kernel_launch(void* const* d_in, const int* in_sizes, int n_in,
                              void* d_out, int out_size) {
    const float* E = (const float*)d_in[0];
    const int* pairs = (const int*)d_in[1];
    float* out = (float*)d_out;
    int P = in_sizes[1] / 2;

    static int smem_set = 0;
    if (!smem_set) {
        cudaFuncSetAttribute(k_gemm_mma, cudaFuncAttributeMaxDynamicSharedMemorySize,
                             SMEM_GEMM_BYTES);
        smem_set = 1;
    }

    k_init<<<(N + 255) / 256, 256>>>(out);
    k_scatter<<<(P + 255) / 256, 256>>>(pairs, P);
    k_pneg<<<(N + 255) / 256, 256>>>();
    k_hn<<<N, 128>>>(E);
    k_pos<<<P, 128>>>(E, pairs);
    k_gemm_mma<<<NB * (NB + 1) / 2, 256, SMEM_GEMM_BYTES>>>();
    k_select<<<N, 512>>>();
    k_loss<<<(P + 255) / 256, 256>>>(pairs, out, P);
}

// round 4
// speedup vs baseline: 2.1927x; 1.4462x over previous
#include <cuda_runtime.h>
#include <cuda_bf16.h>
#include <math.h>
#include <stdint.h>

#define N 4096
#define D 512
#define TAU_INV 5.0f
#define KSEL 820          // N - floor(0.8*(N-1)) = 4096 - 3276
#define NB 32             // 128-wide tiles per dim
#define KS2 64            // K per stage (bf16)
#define STG2 8            // D / KS2
#define NBINS 512
#define SMEM_GEMM_BYTES 69632   // 2 stages x 32KB + epilogue 128x132 fp32 tile reuse

// ---- device scratch (allocation-free) ----
__device__ __nv_bfloat16 g_hnh[(size_t)N * D];   // bf16 normalized hard-neg embeddings (4MB)
__device__ float g_S[(size_t)N * N];             // 64MB (fits L2)
__device__ int   g_partner[N];
__device__ int   g_pneg[N];
__device__ float g_posexp[N];
__device__ float g_negsum[N];

__device__ __forceinline__ uint32_t smem_u32(const void* p) {
    uint32_t a;
    asm("{ .reg .u64 t; cvta.to.shared.u64 t, %1; cvt.u32.u64 %0, t; }" : "=r"(a) : "l"(p));
    return a;
}

// ---------------------------------------------------------------- init
__global__ void k_init(float* out) {
    int i = blockIdx.x * blockDim.x + threadIdx.x;
    if (i < N) g_partner[i] = -1;
    if (i == 0) out[0] = 0.0f;
}

__global__ void k_scatter(const int* __restrict__ pairs, int P) {
    int k = blockIdx.x * blockDim.x + threadIdx.x;
    if (k < P) g_partner[pairs[2 * k]] = pairs[2 * k + 1];
}

__global__ void k_pneg() {
    int i = blockIdx.x * blockDim.x + threadIdx.x;
    if (i >= N) return;
    int j = N - 1;
    while (j >= 0 && (j == i || g_partner[j] == i)) j--;
    g_pneg[i] = (j < 0) ? (N - 1) : j;
}

// ---------------------------------------------------------------- hard-neg normalize -> bf16
__global__ __launch_bounds__(128) void k_hn(const float* __restrict__ E) {
    int i = blockIdx.x;
    int pn = g_pneg[i];
    const float* ei = E + (size_t)i * D;
    const float* ep = E + (size_t)pn * D;
    float v[4];
    float ss = 0.0f;
#pragma unroll
    for (int q = 0; q < 4; q++) {
        int d = threadIdx.x + q * 128;
        float m = 0.5f * ei[d] + 0.5f * ep[d];
        v[q] = m;
        ss += m * m;
    }
    __shared__ float red[4];
    for (int off = 16; off; off >>= 1) ss += __shfl_down_sync(0xffffffffu, ss, off);
    if ((threadIdx.x & 31) == 0) red[threadIdx.x >> 5] = ss;
    __syncthreads();
    if (threadIdx.x == 0) {
        float t = red[0] + red[1] + red[2] + red[3];
        red[0] = 1.0f / fmaxf(sqrtf(t), 1e-8f);
    }
    __syncthreads();
    float inv = red[0];
#pragma unroll
    for (int q = 0; q < 4; q++) {
        int d = threadIdx.x + q * 128;
        g_hnh[(size_t)i * D + d] = __float2bfloat16(v[q] * inv);
    }
}

// ---------------------------------------------------------------- pos term per pair (fp32 exact)
__global__ __launch_bounds__(128) void k_pos(const float* __restrict__ E,
                                             const int* __restrict__ pairs) {
    int k = blockIdx.x;
    int i = pairs[2 * k], j = pairs[2 * k + 1];
    int pi = g_partner[i], pj = g_partner[j];
    const float* Ei  = E + (size_t)i * D;
    const float* Ej  = E + (size_t)j * D;
    const float* Epi = E + (size_t)((pi >= 0) ? pi : 0) * D;
    const float* Epj = E + (size_t)((pj >= 0) ? pj : 0) * D;
    float daa = 0.f, dab = 0.f, dbb = 0.f;
#pragma unroll
    for (int q = 0; q < 4; q++) {
        int d = threadIdx.x + q * 128;
        float a = (pi >= 0) ? (1.5f * Ei[d] - 0.5f * Epi[d]) : Ei[d];
        float b = (pj >= 0) ? (1.5f * Ej[d] - 0.5f * Epj[d]) : Ej[d];
        daa = fmaf(a, a, daa);
        dab = fmaf(a, b, dab);
        dbb = fmaf(b, b, dbb);
    }
    __shared__ float raa[4], rab[4], rbb[4];
    unsigned fm = 0xffffffffu;
    for (int off = 16; off; off >>= 1) {
        daa += __shfl_down_sync(fm, daa, off);
        dab += __shfl_down_sync(fm, dab, off);
        dbb += __shfl_down_sync(fm, dbb, off);
    }
    int w = threadIdx.x >> 5, l = threadIdx.x & 31;
    if (l == 0) { raa[w] = daa; rab[w] = dab; rbb[w] = dbb; }
    __syncthreads();
    if (threadIdx.x == 0) {
        float A = raa[0] + raa[1] + raa[2] + raa[3];
        float B = rab[0] + rab[1] + rab[2] + rab[3];
        float C = rbb[0] + rbb[1] + rbb[2] + rbb[3];
        float cosv = B / (fmaxf(sqrtf(A), 1e-8f) * fmaxf(sqrtf(C), 1e-8f));
        g_posexp[k] = expf(cosv * TAU_INV);
    }
}

// ---------------------------------------------------------------- bf16 mma GEMM
__device__ __forceinline__ void mma16(float* c, const uint32_t* a, const uint32_t* b) {
    asm volatile(
        "mma.sync.aligned.m16n8k16.row.col.f32.bf16.bf16.f32 "
        "{%0,%1,%2,%3}, {%4,%5,%6,%7}, {%8,%9}, {%0,%1,%2,%3};"
        : "+f"(c[0]), "+f"(c[1]), "+f"(c[2]), "+f"(c[3])
        : "r"(a[0]), "r"(a[1]), "r"(a[2]), "r"(a[3]), "r"(b[0]), "r"(b[1]));
}

__device__ __forceinline__ void ldsm_x4(uint32_t* r, uint32_t addr) {
    asm volatile("ldmatrix.sync.aligned.m8n8.x4.shared.b16 {%0,%1,%2,%3}, [%4];"
                 : "=r"(r[0]), "=r"(r[1]), "=r"(r[2]), "=r"(r[3]) : "r"(addr));
}

__device__ __forceinline__ void ldsm_x2(uint32_t* r, uint32_t addr) {
    asm volatile("ldmatrix.sync.aligned.m8n8.x2.shared.b16 {%0,%1}, [%2];"
                 : "=r"(r[0]), "=r"(r[1]) : "r"(addr));
}

__device__ __forceinline__ void cp16(uint32_t dst, const void* src) {
    asm volatile("cp.async.cg.shared.global [%0], [%1], 16;" :: "r"(dst), "l"(src));
}

// S = HN * HN^T, upper-triangle 128x128 tiles + mirror store.
// Stage buffer p (p=0,1): A at p*32768 (128 rows x 128B, chunk-swizzled), B at +16384.
__global__ __launch_bounds__(256) void k_gemm_bf16() {
    extern __shared__ char sm[];
    uint32_t sbase = smem_u32(sm);
    int tid = threadIdx.x;
    int lane = tid & 31, warp = tid >> 5;
    int wm = warp >> 2, wn = warp & 3;   // 2(M) x 4(N) warps, warp tile 64x32

    int t = blockIdx.x, by = 0, rem = t;
    while (rem >= (NB - by)) { rem -= (NB - by); ++by; }
    int bx = by + rem;   // bx >= by

    const __nv_bfloat16* Abase = g_hnh + (size_t)by * 128 * D;
    const __nv_bfloat16* Bbase = g_hnh + (size_t)bx * 128 * D;

    float acc[4][4][4];
#pragma unroll
    for (int im = 0; im < 4; im++)
#pragma unroll
        for (int in = 0; in < 4; in++)
#pragma unroll
            for (int r = 0; r < 4; r++) acc[im][in][r] = 0.0f;

    // async loader: stage s -> buffer p (each thread: 4 x 16B per matrix)
    auto async_load = [&](int s, int p) {
        uint32_t dstA = sbase + p * 32768;
        uint32_t dstB = dstA + 16384;
        int k0 = s * KS2;
#pragma unroll
        for (int q = 0; q < 4; q++) {
            int id = tid + q * 256;          // 0..1023
            int row = id >> 3, c = id & 7;
            uint32_t off = (uint32_t)(row * 128 + ((c ^ (row & 7)) << 4));
            cp16(dstA + off, Abase + (size_t)row * D + k0 + c * 8);
            cp16(dstB + off, Bbase + (size_t)row * D + k0 + c * 8);
        }
        asm volatile("cp.async.commit_group;" ::: "memory");
    };

    // ldmatrix address prep (per-lane constants)
    int g = lane >> 3, r8 = lane & 7;
    int ahi = g >> 1;                        // A k-chunk hi bit
    uint32_t arow[4]; int asw[4];
    int bhi = (lane >> 3) & 1;
    uint32_t brow[4]; int bsw[4];

    auto compute = [&](int p) {
        uint32_t sA = sbase + p * 32768;
        uint32_t sB = sA + 16384;
#pragma unroll
        for (int im = 0; im < 4; im++) {
            int rowA = wm * 64 + im * 16 + r8 + (g & 1) * 8;
            arow[im] = sA + rowA * 128;
            asw[im] = rowA & 7;
        }
#pragma unroll
        for (int in = 0; in < 4; in++) {
            int rowB = wn * 32 + in * 8 + r8;
            brow[in] = sB + rowB * 128;
            bsw[in] = rowB & 7;
        }
#pragma unroll
        for (int ks = 0; ks < 4; ks++) {
            uint32_t a[4][4], b[4][2];
#pragma unroll
            for (int im = 0; im < 4; im++)
                ldsm_x4(a[im], arow[im] + (uint32_t)((((ks << 1) | ahi) ^ asw[im]) << 4));
#pragma unroll
            for (int in = 0; in < 4; in++)
                ldsm_x2(b[in], brow[in] + (uint32_t)((((ks << 1) | bhi) ^ bsw[in]) << 4));
#pragma unroll
            for (int im = 0; im < 4; im++)
#pragma unroll
                for (int in = 0; in < 4; in++) mma16(acc[im][in], a[im], b[in]);
        }
    };

    async_load(0, 0);
    for (int s = 0; s < STG2; s++) {
        if (s + 1 < STG2) async_load(s + 1, (s + 1) & 1);
        if (s + 1 < STG2)
            asm volatile("cp.async.wait_group 1;" ::: "memory");
        else
            asm volatile("cp.async.wait_group 0;" ::: "memory");
        __syncthreads();
        compute(s & 1);
        __syncthreads();
    }

    // ---- epilogue via 128x132 fp32 smem tile (direct + mirror, coalesced) ----
    float* stg = (float*)sm;
#pragma unroll
    for (int im = 0; im < 4; im++) {
        int row = wm * 64 + im * 16 + (lane >> 2);
#pragma unroll
        for (int in = 0; in < 4; in++) {
            int col = wn * 32 + in * 8 + (lane & 3) * 2;
            stg[row * 132 + col]           = acc[im][in][0];
            stg[row * 132 + col + 1]       = acc[im][in][1];
            stg[(row + 8) * 132 + col]     = acc[im][in][2];
            stg[(row + 8) * 132 + col + 1] = acc[im][in][3];
        }
    }
    __syncthreads();

    float* __restrict__ S = g_S;
    int r0 = by * 128, c0 = bx * 128;
#pragma unroll
    for (int q = 0; q < 16; q++) {
        int v = tid + q * 256;
        int row = v >> 5, c4 = (v & 31) << 2;
        float4 x = *(const float4*)(stg + row * 132 + c4);
        *(float4*)(S + (size_t)(r0 + row) * N + c0 + c4) = x;
    }
    if (bx != by) {
#pragma unroll
        for (int q = 0; q < 16; q++) {
            int v = tid + q * 256;
            int col = v >> 5, r4 = (v & 31) << 2;
            float4 x;
            x.x = stg[(r4 + 0) * 132 + col];
            x.y = stg[(r4 + 1) * 132 + col];
            x.z = stg[(r4 + 2) * 132 + col];
            x.w = stg[(r4 + 3) * 132 + col];
            *(float4*)(S + (size_t)(c0 + col) * N + r0 + r4) = x;
        }
    }
}

// ---------------------------------------------------------------- per-row top-K selection + sum
__device__ __forceinline__ int bin_of(float v) {
    int b = (int)((v + 1.0f) * 256.0f);
    return b < 0 ? 0 : (b > (NBINS - 1) ? (NBINS - 1) : b);
}

__global__ __launch_bounds__(512) void k_select() {
    __shared__ float sval[N];                        // 16 KB
    __shared__ unsigned short whist[16 * NBINS];     // 16 KB
    __shared__ int   hist[NBINS];
    __shared__ float list[2048];
    __shared__ int   shist[256];
    __shared__ int   s_cnt, s_b, s_kp, s_b2, s_kp2;
    __shared__ float s_thr;
    __shared__ float warpsum[16];

    int row = blockIdx.x;
    int tid = threadIdx.x;
    int lane = tid & 31, w = tid >> 5;
    int pi = g_partner[row];
    const float4* Sr4 = (const float4*)(g_S + (size_t)row * N);

    for (int b = tid; b < 16 * NBINS / 2; b += 512) ((unsigned*)whist)[b] = 0u;
    if (tid < 256) shist[tid] = 0;
    if (tid == 0) { s_cnt = 0; s_thr = -3.0f; s_b = 0; s_kp = 1; s_b2 = 0; s_kp2 = 1; }
    __syncthreads();

    // pass 1 (vectorized): mask, stash, per-warp aggregated histogram
    unsigned short* wh = whist + w * NBINS;
#pragma unroll
    for (int q = 0; q < 2; q++) {
        int j4 = tid + q * 512;              // float4 index, 0..1023
        float4 v4 = Sr4[j4];
        int jb = j4 << 2;
        if (jb + 0 == row || jb + 0 == pi) v4.x = -2.0f;
        if (jb + 1 == row || jb + 1 == pi) v4.y = -2.0f;
        if (jb + 2 == row || jb + 2 == pi) v4.z = -2.0f;
        if (jb + 3 == row || jb + 3 == pi) v4.w = -2.0f;
        ((float4*)sval)[j4] = v4;
        float vv[4] = {v4.x, v4.y, v4.z, v4.w};
#pragma unroll
        for (int c = 0; c < 4; c++) {
            int b = bin_of(vv[c]);
            unsigned mm = __match_any_sync(0xffffffffu, b);
            if ((__ffs(mm) - 1) == lane) wh[b] = (unsigned short)(wh[b] + __popc(mm));
        }
    }
    __syncthreads();

    if (tid < NBINS) {
        int c = 0;
#pragma unroll
        for (int ww = 0; ww < 16; ww++) c += whist[ww * NBINS + tid];
        hist[tid] = c;
    }
    __syncthreads();

    // locate bin containing KSEL-th largest (suffix scan, 16 bins/lane)
    if (tid < 32) {
        int c = 0;
#pragma unroll
        for (int q = 0; q < 16; q++) c += hist[tid * 16 + q];
        int suf = c;
#pragma unroll
        for (int off = 1; off < 32; off <<= 1) {
            int o = __shfl_down_sync(0xffffffffu, suf, off);
            if (tid + off < 32) suf += o;
        }
        int above = suf - c;
        if (above < KSEL && KSEL <= suf) {
            int remk = KSEL - above;
            int b = tid * 16;
            for (int q = 15; q >= 0; q--) {
                int h = hist[tid * 16 + q];
                if (remk <= h) { b = tid * 16 + q; break; }
                remk -= h;
            }
            s_b = b;
            s_kp = remk;
        }
    }
    __syncthreads();
    int bsel = s_b, kp = s_kp;
    float lo = (float)bsel * (1.0f / 256.0f) - 1.0f;

    // gather boundary-bin candidates + 256-bin sub-histogram
#pragma unroll
    for (int q = 0; q < 2; q++) {
        float4 v4 = ((const float4*)sval)[tid + q * 512];
        float vv[4] = {v4.x, v4.y, v4.z, v4.w};
#pragma unroll
        for (int c = 0; c < 4; c++) {
            float v = vv[c];
            if (bin_of(v) == bsel) {
                int idx = atomicAdd(&s_cnt, 1);
                if (idx < 2048) list[idx] = v;
                int sb = (int)((v - lo) * 65536.0f);
                sb = sb < 0 ? 0 : (sb > 255 ? 255 : sb);
                atomicAdd(&shist[sb], 1);
            }
        }
    }
    __syncthreads();
    int cn = min(s_cnt, 2048);

    // locate sub-bin (8 sub-bins/lane)
    if (tid < 32) {
        int c = 0;
#pragma unroll
        for (int q = 0; q < 8; q++) c += shist[tid * 8 + q];
        int suf = c;
#pragma unroll
        for (int off = 1; off < 32; off <<= 1) {
            int o = __shfl_down_sync(0xffffffffu, suf, off);
            if (tid + off < 32) suf += o;
        }
        int above = suf - c;
        if (above < kp && kp <= suf) {
            int remk = kp - above;
            int b = tid * 8;
            for (int q = 7; q >= 0; q--) {
                int h = shist[tid * 8 + q];
                if (remk <= h) { b = tid * 8 + q; break; }
                remk -= h;
            }
            s_b2 = b;
            s_kp2 = remk;
        }
    }
    __syncthreads();
    int sb2 = s_b2, kp2 = s_kp2;

    // exact tie-aware rank within the chosen sub-bin
    for (int t2 = tid; t2 < cn; t2 += 512) {
        float v = list[t2];
        int vs = (int)((v - lo) * 65536.0f);
        vs = vs < 0 ? 0 : (vs > 255 ? 255 : vs);
        if (vs != sb2) continue;
        int gt = 0, eq = 0;
        for (int m = 0; m < cn; m++) {
            float wv = list[m];
            int ws = (int)((wv - lo) * 65536.0f);
            ws = ws < 0 ? 0 : (ws > 255 ? 255 : ws);
            if (ws == sb2) { gt += (wv > v); eq += (wv == v); }
        }
        if (gt < kp2 && kp2 <= gt + eq) s_thr = v;
    }
    __syncthreads();
    float thr = s_thr;

    // sum exp(s/TAU) over s >= thr (== top-KSEL incl. ties)
    float acc = 0.0f;
#pragma unroll
    for (int q = 0; q < 2; q++) {
        float4 v4 = ((const float4*)sval)[tid + q * 512];
        if (v4.x >= thr) acc += __expf(v4.x * TAU_INV);
        if (v4.y >= thr) acc += __expf(v4.y * TAU_INV);
        if (v4.z >= thr) acc += __expf(v4.z * TAU_INV);
        if (v4.w >= thr) acc += __expf(v4.w * TAU_INV);
    }
    for (int off = 16; off; off >>= 1) acc += __shfl_down_sync(0xffffffffu, acc, off);
    if (lane == 0) warpsum[w] = acc;
    __syncthreads();
    if (tid < 16) {
        float x = warpsum[tid];
        for (int off = 8; off; off >>= 1) x += __shfl_down_sync(0x0000ffffu, x, off);
        if (tid == 0) g_negsum[row] = x;
    }
}

// ---------------------------------------------------------------- final loss reduction
__global__ void k_loss(const int* __restrict__ pairs, float* out, int P) {
    int k = blockIdx.x * blockDim.x + threadIdx.x;
    if (k >= P) return;
    int i = pairs[2 * k];
    float pz = g_posexp[k];
    float ns = g_negsum[i];
    float loss = -logf(pz / (pz + ns));
    atomicAdd(out, loss * (1.0f / (float)P));
}

// ---------------------------------------------------------------- launch
extern "C" void kernel_launch(void* const* d_in, const int* in_sizes, int n_in,
                              void* d_out, int out_size) {
    const float* E = (const float*)d_in[0];
    const int* pairs = (const int*)d_in[1];
    float* out = (float*)d_out;
    int P = in_sizes[1] / 2;

    static int smem_set = 0;
    if (!smem_set) {
        cudaFuncSetAttribute(k_gemm_bf16, cudaFuncAttributeMaxDynamicSharedMemorySize,
                             SMEM_GEMM_BYTES);
        smem_set = 1;
    }

    k_init<<<(N + 255) / 256, 256>>>(out);
    k_scatter<<<(P + 255) / 256, 256>>>(pairs, P);
    k_pneg<<<(N + 255) / 256, 256>>>();
    k_hn<<<N, 128>>>(E);
    k_pos<<<P, 128>>>(E, pairs);
    k_gemm_bf16<<<NB * (NB + 1) / 2, 256, SMEM_GEMM_BYTES>>>();
    k_select<<<N, 512>>>();
    k_loss<<<(P + 255) / 256, 256>>>(pairs, out, P);
}